// round 12
// baseline (speedup 1.0000x reference)
#include <cuda_runtime.h>
#include <cuda_fp16.h>
#include <math.h>
#include <cstdint>

#define Ndim 32
#define Cdim 512
#define Tdim 1024
#define NT   32768
#define NB   2048
#define CT   (Cdim*Tdim)
#define XSZ  (Ndim*Cdim*Tdim)

#define OFF_XD   0
#define OFF_LOSS 16777216
#define OFF_PERP 16777217
#define OFF_CB   16777218
#define OFF_CSE  (OFF_CB + NB*Cdim)
#define OFF_CNT  (OFF_CSE + NB*Cdim)

// Scratch (device globals: the sanctioned no-cudaMalloc path)
__device__ __align__(16) float g_cc[NB];
__device__ __align__(16) int   g_idx[NT];
__device__ __align__(16) float g_nsum[NB*Cdim];
__device__ __align__(16) float g_ncnt[NB];
__device__ float g_loss;
__device__ __align__(16) __half g_dhat[(size_t)NT * NB];  // 128 MB fp16 approx distances
__device__ __align__(16) float g_xT[(size_t)NT * Cdim];   // 64 MB x transposed [row][c]
__device__ __align__(16) int g_hist[NB];
__device__ __align__(16) int g_start[NB];
__device__ __align__(16) int g_cursor[NB];
__device__ __align__(16) int g_bucket[NT];

// ---------------------------------------------------------------- helpers
__device__ __forceinline__ void cp_async16(uint32_t saddr, const void* g) {
    asm volatile("cp.async.ca.shared.global [%0], [%1], 16;" :: "r"(saddr), "l"(g));
}
__device__ __forceinline__ void cp_commit() {
    asm volatile("cp.async.commit_group;" ::: "memory");
}
__device__ __forceinline__ void mma_tf32(float* d, const uint32_t* a, const uint32_t* b) {
    asm volatile(
        "mma.sync.aligned.m16n8k8.row.col.f32.tf32.tf32.f32 "
        "{%0,%1,%2,%3}, {%4,%5,%6,%7}, {%8,%9}, {%0,%1,%2,%3};"
        : "+f"(d[0]), "+f"(d[1]), "+f"(d[2]), "+f"(d[3])
        : "r"(a[0]), "r"(a[1]), "r"(a[2]), "r"(a[3]), "r"(b[0]), "r"(b[1]));
}

// ---------------- 0: zero scratch ----------------
__global__ void zero_kernel() {
    int i = blockIdx.x * 256 + threadIdx.x;
    if (i < NB) g_hist[i] = 0;
    if (i == 0) g_loss = 0.0f;
}

// ---------------- 1: codebook squared norms ----------------
__global__ void norms_kernel(const float* __restrict__ cb) {
    int warp = threadIdx.x >> 5, lane = threadIdx.x & 31;
    int code = blockIdx.x * 8 + warp;
    const float* row = cb + (size_t)code * Cdim;
    float s = 0.0f;
    for (int j = lane; j < Cdim; j += 32) { float v = row[j]; s += v * v; }
    #pragma unroll
    for (int o = 16; o > 0; o >>= 1) s += __shfl_xor_sync(0xffffffffu, s, o);
    if (lane == 0) g_cc[code] = s;
}

// ---------------- 2: transpose x -> xT[row][c] ----------------
__global__ void transpose_kernel(const float* __restrict__ x) {
    __shared__ float s[32][33];
    int b = blockIdx.x;
    int ct = b & 15;          // c tile (16)
    int tt = (b >> 4) & 31;   // t tile (32)
    int n  = b >> 9;          // batch (32)
    int tid = threadIdx.x;
    int l5 = tid & 31, h3 = tid >> 5;
    #pragma unroll
    for (int q = 0; q < 4; q++) {
        int c_l = h3 + q * 8;
        s[c_l][l5] = x[(size_t)n * CT + (size_t)(ct * 32 + c_l) * Tdim + tt * 32 + l5];
    }
    __syncthreads();
    #pragma unroll
    for (int q = 0; q < 4; q++) {
        int t_l = h3 + q * 8;
        g_xT[(size_t)(n * 1024 + tt * 32 + t_l) * Cdim + ct * 32 + l5] = s[l5][t_l];
    }
}

// ---------------- 3: TF32 mma.sync screen GEMM -> d_hat (fp16) ----------------
// 3-stage cp.async pipeline, ONE barrier per iter. PROVEN 532us/42.5% binary — do not edit.
#define BM 128
#define BN 128
#define BK 32
#define AS_STRIDE 136
#define BS_STRIDE 36
#define AS_FLOATS (BK * AS_STRIDE)                 // 4352
#define BS_FLOATS (BN * BS_STRIDE)                 // 4608
#define STAGE_FLOATS (AS_FLOATS + BS_FLOATS)       // 8960
#define SMEM_BYTES (3 * STAGE_FLOATS * 4)          // 107520

__global__ __launch_bounds__(256, 2) void gemm_dhat(const float* __restrict__ x,
                                                    const float* __restrict__ cb) {
    extern __shared__ float sm[];
    uint32_t smbase = (uint32_t)__cvta_generic_to_shared(sm);

    int tid = threadIdx.x, lane = tid & 31, wid = tid >> 5;
    int wm = wid >> 2, wn = wid & 3;       // warp grid 2 (m) x 4 (n)
    int lq = lane & 3, lr = lane >> 2;
    int r0 = blockIdx.x * BM;
    const float* xb = x + (size_t)(r0 >> 10) * CT + (r0 & 1023);

    int a_p  = (tid & 31) << 2;  // float offset within a k-row (0..124)
    int a_kb = tid >> 5;         // base k (0..7)
    int b_kp = (tid & 7) << 2;   // float offset within code row
    int b_cb = tid >> 3;         // base code (0..31)

    float acc[4][4][4];
    #pragma unroll
    for (int mi = 0; mi < 4; mi++)
        #pragma unroll
        for (int ni = 0; ni < 4; ni++)
            #pragma unroll
            for (int v = 0; v < 4; v++) acc[mi][ni][v] = 0.0f;

    auto load_tiles = [&](int stage, int idx) {
        int nt = (idx >> 4) * 128, kc = (idx & 15) * 32;
        uint32_t sA = smbase + (uint32_t)(stage * STAGE_FLOATS) * 4u;
        uint32_t sB = sA + (uint32_t)AS_FLOATS * 4u;
        #pragma unroll
        for (int it = 0; it < 4; it++) {
            int k = a_kb + it * 8;
            cp_async16(sA + (uint32_t)(k * AS_STRIDE + a_p) * 4u,
                       xb + (size_t)(kc + k) * Tdim + a_p);
        }
        #pragma unroll
        for (int it = 0; it < 4; it++) {
            int code = b_cb + it * 32;
            cp_async16(sB + (uint32_t)(code * BS_STRIDE + b_kp) * 4u,
                       cb + (size_t)(nt + code) * Cdim + kc + b_kp);
        }
    };

    load_tiles(0, 0); cp_commit();
    load_tiles(1, 1); cp_commit();
    asm volatile("cp.async.wait_group 1;" ::: "memory");   // stage 0 landed (all threads, pre-bar)

    for (int i = 0; i < 256; i++) {            // (nt, kc) flattened: 16 x 16
        __syncthreads();                       // opens epoch i: stage i%3 published, overwrite-safe
        if (i + 2 < 256) load_tiles((i + 2) % 3, i + 2);
        cp_commit();
        asm volatile("cp.async.wait_group 1;" ::: "memory");  // data <= i+1 landed (this thread)

        const float* A = sm + (i % 3) * STAGE_FLOATS;
        const float* B = A + AS_FLOATS;
        #pragma unroll
        for (int kk = 0; kk < 4; kk++) {
            uint32_t a[4][4], b[4][2];
            #pragma unroll
            for (int mi = 0; mi < 4; mi++) {
                const float* ap = A + (kk * 8 + lq) * AS_STRIDE + wm * 64 + mi * 16 + lr;
                a[mi][0] = __float_as_uint(ap[0]);
                a[mi][1] = __float_as_uint(ap[8]);
                a[mi][2] = __float_as_uint(ap[4 * AS_STRIDE]);
                a[mi][3] = __float_as_uint(ap[4 * AS_STRIDE + 8]);
            }
            #pragma unroll
            for (int ni = 0; ni < 4; ni++) {
                const float* bp = B + (wn * 32 + ni * 8 + lr) * BS_STRIDE + kk * 8 + lq;
                b[ni][0] = __float_as_uint(bp[0]);
                b[ni][1] = __float_as_uint(bp[4]);
            }
            #pragma unroll
            for (int mi = 0; mi < 4; mi++)
                #pragma unroll
                for (int ni = 0; ni < 4; ni++)
                    mma_tf32(acc[mi][ni], a[mi], b[ni]);
        }

        if ((i & 15) == 15) {  // end of K for this n-tile: spill d_hat (fp16), reset accs
            int nt = (i >> 4) * 128;
            #pragma unroll
            for (int mi = 0; mi < 4; mi++) {
                int row = r0 + wm * 64 + mi * 16 + lr;
                #pragma unroll
                for (int ni = 0; ni < 4; ni++) {
                    int col = nt + wn * 32 + ni * 8 + 2 * lq;
                    float cc0 = __ldg(&g_cc[col]);
                    float cc1 = __ldg(&g_cc[col + 1]);
                    float2 v0 = make_float2(cc0 - 2.0f * acc[mi][ni][0],
                                            cc1 - 2.0f * acc[mi][ni][1]);
                    float2 v1 = make_float2(cc0 - 2.0f * acc[mi][ni][2],
                                            cc1 - 2.0f * acc[mi][ni][3]);
                    *(__half2*)&g_dhat[(size_t)row * NB + col] = __float22half2_rn(v0);
                    *(__half2*)&g_dhat[(size_t)(row + 8) * NB + col] = __float22half2_rn(v1);
                    acc[mi][ni][0] = acc[mi][ni][1] = acc[mi][ni][2] = acc[mi][ni][3] = 0.0f;
                }
            }
        }
    }
}

// ---------------- 4: rescue — exact fp32 argmin among margin candidates (fp16 d_hat) ----------------
// Also histograms winning codes (1 atomic per row).
__global__ void rescue_kernel(const float* __restrict__ cb) {
    int wid = threadIdx.x >> 5, lane = threadIdx.x & 31;
    int row = blockIdx.x * 8 + wid;

    float xr[16];
    #pragma unroll
    for (int q = 0; q < 16; q++)
        xr[q] = g_xT[(size_t)row * Cdim + lane + q * 32];

    const __half2* drow = (const __half2*)&g_dhat[(size_t)row * NB];
    float2 dv[32];
    #pragma unroll
    for (int i = 0; i < 32; i++)
        dv[i] = __half22float2(drow[lane + i * 32]);   // codes 2*(lane+i*32), +1

    float bv = fminf(dv[0].x, dv[0].y);
    #pragma unroll
    for (int i = 1; i < 32; i++) bv = fminf(bv, fminf(dv[i].x, dv[i].y));
    #pragma unroll
    for (int o = 16; o > 0; o >>= 1) bv = fminf(bv, __shfl_xor_sync(0xffffffffu, bv, o));

    float thr = bv + 8.0f;
    float bestE = 3.0e38f;
    int   bestI = 0x7fffffff;

    auto exact = [&](int j) {
        const float* crow = cb + (size_t)j * Cdim;
        float p = 0.0f;
        #pragma unroll
        for (int q = 0; q < 16; q++)
            p += xr[q] * __ldg(&crow[lane + q * 32]);
        #pragma unroll
        for (int o = 16; o > 0; o >>= 1) p += __shfl_xor_sync(0xffffffffu, p, o);
        float d = __ldg(&g_cc[j]) - 2.0f * p;
        if (d < bestE || (d == bestE && j < bestI)) { bestE = d; bestI = j; }
    };

    #pragma unroll 4
    for (int i = 0; i < 32; i++) {
        unsigned mlo = __ballot_sync(0xffffffffu, dv[i].x <= thr);
        unsigned mhi = __ballot_sync(0xffffffffu, dv[i].y <= thr);
        while (mlo) { int s = __ffs(mlo) - 1; mlo &= mlo - 1; exact((i * 32 + s) * 2); }
        while (mhi) { int s = __ffs(mhi) - 1; mhi &= mhi - 1; exact((i * 32 + s) * 2 + 1); }
    }
    if (lane == 0) {
        g_idx[row] = bestI;
        atomicAdd(&g_hist[bestI], 1);
    }
}

// ---------------- 5: prefix sum over histogram -> starts, cursors, float counts ----------------
__global__ void prefix_kernel() {
    __shared__ int part[256];
    __shared__ int psum[256];
    int tid = threadIdx.x;
    int base = tid * 8;
    int loc[8];
    int s = 0;
    #pragma unroll
    for (int j = 0; j < 8; j++) { loc[j] = g_hist[base + j]; s += loc[j]; }
    part[tid] = s;
    __syncthreads();
    if (tid == 0) {
        int run = 0;
        for (int i = 0; i < 256; i++) { psum[i] = run; run += part[i]; }
    }
    __syncthreads();
    int run = psum[tid];
    #pragma unroll
    for (int j = 0; j < 8; j++) {
        g_start[base + j]  = run;
        g_cursor[base + j] = run;
        g_ncnt[base + j]   = (float)loc[j];
        run += loc[j];
    }
}

// ---------------- 6: fill buckets (row ids grouped by code) ----------------
__global__ void fill_kernel() {
    int row = blockIdx.x * 256 + threadIdx.x;
    int code = g_idx[row];
    int pos = atomicAdd(&g_cursor[code], 1);
    g_bucket[pos] = row;
}

// ---------------- 7: dense per-code segment sum (no atomics) ----------------
__global__ __launch_bounds__(128) void codesum_kernel() {
    int code = blockIdx.x;
    int start = g_start[code];
    int cnt   = g_hist[code];
    int c4 = threadIdx.x * 4;
    float4 acc = make_float4(0.f, 0.f, 0.f, 0.f);
    for (int i = 0; i < cnt; i++) {
        int row = g_bucket[start + i];
        float4 v = *(const float4*)&g_xT[(size_t)row * Cdim + c4];
        acc.x += v.x; acc.y += v.y; acc.z += v.z; acc.w += v.w;
    }
    *(float4*)&g_nsum[(size_t)code * Cdim + c4] = acc;
}

// ---------------- 8: x_d output + commit-loss partial ----------------
__global__ void out_kernel(const float* __restrict__ x, const float* __restrict__ cb,
                           float* __restrict__ out) {
    int gi = (blockIdx.x * 256 + threadIdx.x) << 2;
    int n = gi >> 19;
    int rem = gi & (CT - 1);
    int c = rem >> 10;
    int t = rem & 1023;
    int row = (n << 10) + t;
    float4 xv = *(const float4*)(x + gi);
    int4 idx = *(const int4*)(g_idx + row);
    float4 o;
    o.x = cb[(size_t)idx.x * Cdim + c];
    o.y = cb[(size_t)idx.y * Cdim + c];
    o.z = cb[(size_t)idx.z * Cdim + c];
    o.w = cb[(size_t)idx.w * Cdim + c];
    *(float4*)(out + OFF_XD + gi) = o;
    float dx = xv.x - o.x, dy = xv.y - o.y, dz = xv.z - o.z, dw = xv.w - o.w;
    float s = dx * dx + dy * dy + dz * dz + dw * dw;
    #pragma unroll
    for (int off = 16; off > 0; off >>= 1) s += __shfl_xor_sync(0xffffffffu, s, off);
    __shared__ float sh[8];
    int lane = threadIdx.x & 31, w = threadIdx.x >> 5;
    if (lane == 0) sh[w] = s;
    __syncthreads();
    if (threadIdx.x == 0) {
        float tot = 0.0f;
        #pragma unroll
        for (int i = 0; i < 8; i++) tot += sh[i];
        atomicAdd(&g_loss, tot);
    }
}

// ---------------- 9: EMA update + codebook reset + count out ----------------
__global__ void ema_kernel(const float* __restrict__ x,
                           const float* __restrict__ code_sum,
                           const float* __restrict__ code_count,
                           float* __restrict__ out) {
    int gi = blockIdx.x * 256 + threadIdx.x;
    int code = gi >> 9;
    int c = gi & 511;
    float cse = 0.99f * code_sum[gi] + 0.01f * g_nsum[gi];
    float cnt = 0.99f * code_count[code] + 0.01f * g_ncnt[code];
    out[OFF_CSE + gi] = cse;
    float ncb;
    if (cnt >= 1.0f) {
        ncb = cse / fmaxf(cnt, 1e-10f);
    } else {
        int t = code & 1023;
        int n = code >> 10;
        ncb = x[(size_t)n * CT + (size_t)c * Tdim + t];
    }
    out[OFF_CB + gi] = ncb;
    if (c == 0) out[OFF_CNT + code] = cnt;
}

// ---------------- 10: perplexity + loss finalize ----------------
__global__ void finalize_kernel(float* __restrict__ out) {
    float h = 0.0f;
    for (int code = threadIdx.x; code < NB; code += 256) {
        float p = g_ncnt[code] * (1.0f / 32768.0f);
        h += p * logf(p + 1e-7f);
    }
    #pragma unroll
    for (int off = 16; off > 0; off >>= 1) h += __shfl_xor_sync(0xffffffffu, h, off);
    __shared__ float sh[8];
    int lane = threadIdx.x & 31, w = threadIdx.x >> 5;
    if (lane == 0) sh[w] = h;
    __syncthreads();
    if (threadIdx.x == 0) {
        float tot = 0.0f;
        #pragma unroll
        for (int i = 0; i < 8; i++) tot += sh[i];
        out[OFF_PERP] = expf(-tot);
        out[OFF_LOSS] = g_loss * (1.0f / (float)XSZ);
    }
}

extern "C" void kernel_launch(void* const* d_in, const int* in_sizes, int n_in,
                              void* d_out, int out_size) {
    const float* x    = (const float*)d_in[0];
    const float* cb   = (const float*)d_in[1];
    const float* csum = (const float*)d_in[2];
    const float* ccnt = (const float*)d_in[3];
    float* out = (float*)d_out;

    cudaFuncSetAttribute(gemm_dhat, cudaFuncAttributeMaxDynamicSharedMemorySize, SMEM_BYTES);

    zero_kernel     <<<(NB + 255) / 256, 256>>>();
    norms_kernel    <<<NB / 8, 256>>>(cb);
    transpose_kernel<<<Ndim * 32 * 16, 256>>>(x);
    gemm_dhat       <<<NT / BM, 256, SMEM_BYTES>>>(x, cb);
    rescue_kernel   <<<NT / 8, 256>>>(cb);
    prefix_kernel   <<<1, 256>>>();
    fill_kernel     <<<NT / 256, 256>>>();
    codesum_kernel  <<<NB, 128>>>();
    out_kernel      <<<XSZ / 4 / 256, 256>>>(x, cb, out);
    ema_kernel      <<<NB * Cdim / 256, 256>>>(x, csum, ccnt, out);
    finalize_kernel <<<1, 256>>>(out);
}

// round 14
// speedup vs baseline: 1.1932x; 1.1932x over previous
#include <cuda_runtime.h>
#include <cuda_fp16.h>
#include <math.h>
#include <cstdint>

#define Ndim 32
#define Cdim 512
#define Tdim 1024
#define NT   32768
#define NB   2048
#define CT   (Cdim*Tdim)
#define XSZ  (Ndim*Cdim*Tdim)

#define OFF_XD   0
#define OFF_LOSS 16777216
#define OFF_PERP 16777217
#define OFF_CB   16777218
#define OFF_CSE  (OFF_CB + NB*Cdim)
#define OFF_CNT  (OFF_CSE + NB*Cdim)

// Scratch (device globals: the sanctioned no-cudaMalloc path)
__device__ __align__(16) float g_cc[NB];
__device__ __align__(16) int   g_idx[NT];
__device__ __align__(16) float g_nsum[NB*Cdim];
__device__ __align__(16) float g_ncnt[NB];
__device__ float g_loss;
__device__ __align__(16) __half g_dhat[(size_t)NT * NB];  // 128 MB fp16 approx distances
__device__ __align__(16) float g_xT[(size_t)NT * Cdim];   // 64 MB x transposed [row][c]

// ---------------------------------------------------------------- helpers
__device__ __forceinline__ void cp_async16(uint32_t saddr, const void* g) {
    asm volatile("cp.async.ca.shared.global [%0], [%1], 16;" :: "r"(saddr), "l"(g));
}
__device__ __forceinline__ void cp_commit() {
    asm volatile("cp.async.commit_group;" ::: "memory");
}
__device__ __forceinline__ void mma_tf32(float* d, const uint32_t* a, const uint32_t* b) {
    asm volatile(
        "mma.sync.aligned.m16n8k8.row.col.f32.tf32.tf32.f32 "
        "{%0,%1,%2,%3}, {%4,%5,%6,%7}, {%8,%9}, {%0,%1,%2,%3};"
        : "+f"(d[0]), "+f"(d[1]), "+f"(d[2]), "+f"(d[3])
        : "r"(a[0]), "r"(a[1]), "r"(a[2]), "r"(a[3]), "r"(b[0]), "r"(b[1]));
}

// ---------------- 0: zero scratch ----------------
__global__ void zero_kernel() {
    int i = blockIdx.x * 256 + threadIdx.x;
    if (i < NB * Cdim) g_nsum[i] = 0.0f;
    if (i < NB)        g_ncnt[i] = 0.0f;
    if (i == 0)        g_loss = 0.0f;
}

// ---------------- 1: codebook squared norms ----------------
__global__ void norms_kernel(const float* __restrict__ cb) {
    int warp = threadIdx.x >> 5, lane = threadIdx.x & 31;
    int code = blockIdx.x * 8 + warp;
    const float* row = cb + (size_t)code * Cdim;
    float s = 0.0f;
    for (int j = lane; j < Cdim; j += 32) { float v = row[j]; s += v * v; }
    #pragma unroll
    for (int o = 16; o > 0; o >>= 1) s += __shfl_xor_sync(0xffffffffu, s, o);
    if (lane == 0) g_cc[code] = s;
}

// ---------------- 2: transpose x -> xT[row][c] ----------------
__global__ void transpose_kernel(const float* __restrict__ x) {
    __shared__ float s[32][33];
    int b = blockIdx.x;
    int ct = b & 15;          // c tile (16)
    int tt = (b >> 4) & 31;   // t tile (32)
    int n  = b >> 9;          // batch (32)
    int tid = threadIdx.x;
    int l5 = tid & 31, h3 = tid >> 5;
    #pragma unroll
    for (int q = 0; q < 4; q++) {
        int c_l = h3 + q * 8;
        s[c_l][l5] = x[(size_t)n * CT + (size_t)(ct * 32 + c_l) * Tdim + tt * 32 + l5];
    }
    __syncthreads();
    #pragma unroll
    for (int q = 0; q < 4; q++) {
        int t_l = h3 + q * 8;
        g_xT[(size_t)(n * 1024 + tt * 32 + t_l) * Cdim + ct * 32 + l5] = s[l5][t_l];
    }
}

// ---------------- 3: TF32 mma.sync screen GEMM -> d_hat (fp16) ----------------
// 3-stage cp.async pipeline, ONE barrier per iter. PROVEN 532us/42.5% binary — do not edit.
#define BM 128
#define BN 128
#define BK 32
#define AS_STRIDE 136
#define BS_STRIDE 36
#define AS_FLOATS (BK * AS_STRIDE)                 // 4352
#define BS_FLOATS (BN * BS_STRIDE)                 // 4608
#define STAGE_FLOATS (AS_FLOATS + BS_FLOATS)       // 8960
#define SMEM_BYTES (3 * STAGE_FLOATS * 4)          // 107520

__global__ __launch_bounds__(256, 2) void gemm_dhat(const float* __restrict__ x,
                                                    const float* __restrict__ cb) {
    extern __shared__ float sm[];
    uint32_t smbase = (uint32_t)__cvta_generic_to_shared(sm);

    int tid = threadIdx.x, lane = tid & 31, wid = tid >> 5;
    int wm = wid >> 2, wn = wid & 3;       // warp grid 2 (m) x 4 (n)
    int lq = lane & 3, lr = lane >> 2;
    int r0 = blockIdx.x * BM;
    const float* xb = x + (size_t)(r0 >> 10) * CT + (r0 & 1023);

    int a_p  = (tid & 31) << 2;  // float offset within a k-row (0..124)
    int a_kb = tid >> 5;         // base k (0..7)
    int b_kp = (tid & 7) << 2;   // float offset within code row
    int b_cb = tid >> 3;         // base code (0..31)

    float acc[4][4][4];
    #pragma unroll
    for (int mi = 0; mi < 4; mi++)
        #pragma unroll
        for (int ni = 0; ni < 4; ni++)
            #pragma unroll
            for (int v = 0; v < 4; v++) acc[mi][ni][v] = 0.0f;

    auto load_tiles = [&](int stage, int idx) {
        int nt = (idx >> 4) * 128, kc = (idx & 15) * 32;
        uint32_t sA = smbase + (uint32_t)(stage * STAGE_FLOATS) * 4u;
        uint32_t sB = sA + (uint32_t)AS_FLOATS * 4u;
        #pragma unroll
        for (int it = 0; it < 4; it++) {
            int k = a_kb + it * 8;
            cp_async16(sA + (uint32_t)(k * AS_STRIDE + a_p) * 4u,
                       xb + (size_t)(kc + k) * Tdim + a_p);
        }
        #pragma unroll
        for (int it = 0; it < 4; it++) {
            int code = b_cb + it * 32;
            cp_async16(sB + (uint32_t)(code * BS_STRIDE + b_kp) * 4u,
                       cb + (size_t)(nt + code) * Cdim + kc + b_kp);
        }
    };

    load_tiles(0, 0); cp_commit();
    load_tiles(1, 1); cp_commit();
    asm volatile("cp.async.wait_group 1;" ::: "memory");   // stage 0 landed (all threads, pre-bar)

    for (int i = 0; i < 256; i++) {            // (nt, kc) flattened: 16 x 16
        __syncthreads();                       // opens epoch i: stage i%3 published, overwrite-safe
        if (i + 2 < 256) load_tiles((i + 2) % 3, i + 2);
        cp_commit();
        asm volatile("cp.async.wait_group 1;" ::: "memory");  // data <= i+1 landed (this thread)

        const float* A = sm + (i % 3) * STAGE_FLOATS;
        const float* B = A + AS_FLOATS;
        #pragma unroll
        for (int kk = 0; kk < 4; kk++) {
            uint32_t a[4][4], b[4][2];
            #pragma unroll
            for (int mi = 0; mi < 4; mi++) {
                const float* ap = A + (kk * 8 + lq) * AS_STRIDE + wm * 64 + mi * 16 + lr;
                a[mi][0] = __float_as_uint(ap[0]);
                a[mi][1] = __float_as_uint(ap[8]);
                a[mi][2] = __float_as_uint(ap[4 * AS_STRIDE]);
                a[mi][3] = __float_as_uint(ap[4 * AS_STRIDE + 8]);
            }
            #pragma unroll
            for (int ni = 0; ni < 4; ni++) {
                const float* bp = B + (wn * 32 + ni * 8 + lr) * BS_STRIDE + kk * 8 + lq;
                b[ni][0] = __float_as_uint(bp[0]);
                b[ni][1] = __float_as_uint(bp[4]);
            }
            #pragma unroll
            for (int mi = 0; mi < 4; mi++)
                #pragma unroll
                for (int ni = 0; ni < 4; ni++)
                    mma_tf32(acc[mi][ni], a[mi], b[ni]);
        }

        if ((i & 15) == 15) {  // end of K for this n-tile: spill d_hat (fp16), reset accs
            int nt = (i >> 4) * 128;
            #pragma unroll
            for (int mi = 0; mi < 4; mi++) {
                int row = r0 + wm * 64 + mi * 16 + lr;
                #pragma unroll
                for (int ni = 0; ni < 4; ni++) {
                    int col = nt + wn * 32 + ni * 8 + 2 * lq;
                    float cc0 = __ldg(&g_cc[col]);
                    float cc1 = __ldg(&g_cc[col + 1]);
                    float2 v0 = make_float2(cc0 - 2.0f * acc[mi][ni][0],
                                            cc1 - 2.0f * acc[mi][ni][1]);
                    float2 v1 = make_float2(cc0 - 2.0f * acc[mi][ni][2],
                                            cc1 - 2.0f * acc[mi][ni][3]);
                    *(__half2*)&g_dhat[(size_t)row * NB + col] = __float22half2_rn(v0);
                    *(__half2*)&g_dhat[(size_t)(row + 8) * NB + col] = __float22half2_rn(v1);
                    acc[mi][ni][0] = acc[mi][ni][1] = acc[mi][ni][2] = acc[mi][ni][3] = 0.0f;
                }
            }
        }
    }
}

// ---------------- 4: rescue — exact fp32 argmin among margin candidates (fp16 d_hat) ----------------
// Screen error: tf32 <= 2.7 each side + fp16 quant 0.25 each side => 5.9 < margin 8.0.
__global__ void rescue_kernel(const float* __restrict__ cb) {
    int wid = threadIdx.x >> 5, lane = threadIdx.x & 31;
    int row = blockIdx.x * 8 + wid;

    float xr[16];
    #pragma unroll
    for (int q = 0; q < 16; q++)
        xr[q] = g_xT[(size_t)row * Cdim + lane + q * 32];

    const __half2* drow = (const __half2*)&g_dhat[(size_t)row * NB];
    float2 dv[32];
    #pragma unroll
    for (int i = 0; i < 32; i++)
        dv[i] = __half22float2(drow[lane + i * 32]);   // codes 2*(lane+i*32), +1

    float bv = fminf(dv[0].x, dv[0].y);
    #pragma unroll
    for (int i = 1; i < 32; i++) bv = fminf(bv, fminf(dv[i].x, dv[i].y));
    #pragma unroll
    for (int o = 16; o > 0; o >>= 1) bv = fminf(bv, __shfl_xor_sync(0xffffffffu, bv, o));

    float thr = bv + 8.0f;
    float bestE = 3.0e38f;
    int   bestI = 0x7fffffff;

    auto exact = [&](int j) {
        const float* crow = cb + (size_t)j * Cdim;
        float p = 0.0f;
        #pragma unroll
        for (int q = 0; q < 16; q++)
            p += xr[q] * __ldg(&crow[lane + q * 32]);
        #pragma unroll
        for (int o = 16; o > 0; o >>= 1) p += __shfl_xor_sync(0xffffffffu, p, o);
        float d = __ldg(&g_cc[j]) - 2.0f * p;
        if (d < bestE || (d == bestE && j < bestI)) { bestE = d; bestI = j; }
    };

    #pragma unroll 4
    for (int i = 0; i < 32; i++) {
        unsigned mlo = __ballot_sync(0xffffffffu, dv[i].x <= thr);
        unsigned mhi = __ballot_sync(0xffffffffu, dv[i].y <= thr);
        while (mlo) { int s = __ffs(mlo) - 1; mlo &= mlo - 1; exact((i * 32 + s) * 2); }
        while (mhi) { int s = __ffs(mhi) - 1; mhi &= mhi - 1; exact((i * 32 + s) * 2 + 1); }
    }
    if (lane == 0) g_idx[row] = bestI;
}

// ---------------- 5: warp-per-row coalesced segment-sum scatter ----------------
// Each red.global.add.f32 covers 32 CONSECUTIVE addresses of one code row:
// 1 L2 line per instruction instead of 32 scattered lines.
__global__ void rowscatter_kernel() {
    int wid = threadIdx.x >> 5, lane = threadIdx.x & 31;
    int row = blockIdx.x * 8 + wid;
    int code = g_idx[row];
    const float* xrow = &g_xT[(size_t)row * Cdim];
    float* dst = &g_nsum[(size_t)code * Cdim];
    #pragma unroll
    for (int q = 0; q < 16; q++) {
        int c = lane + q * 32;
        atomicAdd(&dst[c], xrow[c]);
    }
    if (lane == 0) atomicAdd(&g_ncnt[code], 1.0f);
}

// ---------------- 6: x_d output + commit-loss partial (no atomics on nsum) ----------------
__global__ void out_kernel(const float* __restrict__ x, const float* __restrict__ cb,
                           float* __restrict__ out) {
    int gi = (blockIdx.x * 256 + threadIdx.x) << 2;
    int n = gi >> 19;
    int rem = gi & (CT - 1);
    int c = rem >> 10;
    int t = rem & 1023;
    int row = (n << 10) + t;
    float4 xv = *(const float4*)(x + gi);
    int4 idx = *(const int4*)(g_idx + row);
    float4 o;
    o.x = cb[(size_t)idx.x * Cdim + c];
    o.y = cb[(size_t)idx.y * Cdim + c];
    o.z = cb[(size_t)idx.z * Cdim + c];
    o.w = cb[(size_t)idx.w * Cdim + c];
    *(float4*)(out + OFF_XD + gi) = o;
    float dx = xv.x - o.x, dy = xv.y - o.y, dz = xv.z - o.z, dw = xv.w - o.w;
    float s = dx * dx + dy * dy + dz * dz + dw * dw;
    #pragma unroll
    for (int off = 16; off > 0; off >>= 1) s += __shfl_xor_sync(0xffffffffu, s, off);
    __shared__ float sh[8];
    int lane = threadIdx.x & 31, w = threadIdx.x >> 5;
    if (lane == 0) sh[w] = s;
    __syncthreads();
    if (threadIdx.x == 0) {
        float tot = 0.0f;
        #pragma unroll
        for (int i = 0; i < 8; i++) tot += sh[i];
        atomicAdd(&g_loss, tot);
    }
}

// ---------------- 7: EMA update + codebook reset + count out ----------------
__global__ void ema_kernel(const float* __restrict__ x,
                           const float* __restrict__ code_sum,
                           const float* __restrict__ code_count,
                           float* __restrict__ out) {
    int gi = blockIdx.x * 256 + threadIdx.x;
    int code = gi >> 9;
    int c = gi & 511;
    float cse = 0.99f * code_sum[gi] + 0.01f * g_nsum[gi];
    float cnt = 0.99f * code_count[code] + 0.01f * g_ncnt[code];
    out[OFF_CSE + gi] = cse;
    float ncb;
    if (cnt >= 1.0f) {
        ncb = cse / fmaxf(cnt, 1e-10f);
    } else {
        int t = code & 1023;
        int n = code >> 10;
        ncb = x[(size_t)n * CT + (size_t)c * Tdim + t];
    }
    out[OFF_CB + gi] = ncb;
    if (c == 0) out[OFF_CNT + code] = cnt;
}

// ---------------- 8: perplexity + loss finalize ----------------
__global__ void finalize_kernel(float* __restrict__ out) {
    float h = 0.0f;
    for (int code = threadIdx.x; code < NB; code += 256) {
        float p = g_ncnt[code] * (1.0f / 32768.0f);
        h += p * logf(p + 1e-7f);
    }
    #pragma unroll
    for (int off = 16; off > 0; off >>= 1) h += __shfl_xor_sync(0xffffffffu, h, off);
    __shared__ float sh[8];
    int lane = threadIdx.x & 31, w = threadIdx.x >> 5;
    if (lane == 0) sh[w] = h;
    __syncthreads();
    if (threadIdx.x == 0) {
        float tot = 0.0f;
        #pragma unroll
        for (int i = 0; i < 8; i++) tot += sh[i];
        out[OFF_PERP] = expf(-tot);
        out[OFF_LOSS] = g_loss * (1.0f / (float)XSZ);
    }
}

extern "C" void kernel_launch(void* const* d_in, const int* in_sizes, int n_in,
                              void* d_out, int out_size) {
    const float* x    = (const float*)d_in[0];
    const float* cb   = (const float*)d_in[1];
    const float* csum = (const float*)d_in[2];
    const float* ccnt = (const float*)d_in[3];
    float* out = (float*)d_out;

    cudaFuncSetAttribute(gemm_dhat, cudaFuncAttributeMaxDynamicSharedMemorySize, SMEM_BYTES);

    zero_kernel      <<<(NB * Cdim + 255) / 256, 256>>>();
    norms_kernel     <<<NB / 8, 256>>>(cb);
    transpose_kernel <<<Ndim * 32 * 16, 256>>>(x);
    gemm_dhat        <<<NT / BM, 256, SMEM_BYTES>>>(x, cb);
    rescue_kernel    <<<NT / 8, 256>>>(cb);
    rowscatter_kernel<<<NT / 8, 256>>>();
    out_kernel       <<<XSZ / 4 / 256, 256>>>(x, cb, out);
    ema_kernel       <<<NB * Cdim / 256, 256>>>(x, csum, ccnt, out);
    finalize_kernel  <<<1, 256>>>(out);
}

// round 15
// speedup vs baseline: 1.2465x; 1.0446x over previous
#include <cuda_runtime.h>
#include <cuda_fp16.h>
#include <math.h>
#include <cstdint>

#define Ndim 32
#define Cdim 512
#define Tdim 1024
#define NT   32768
#define NB   2048
#define CT   (Cdim*Tdim)
#define XSZ  (Ndim*Cdim*Tdim)

#define OFF_XD   0
#define OFF_LOSS 16777216
#define OFF_PERP 16777217
#define OFF_CB   16777218
#define OFF_CSE  (OFF_CB + NB*Cdim)
#define OFF_CNT  (OFF_CSE + NB*Cdim)

// Scratch (device globals: the sanctioned no-cudaMalloc path)
__device__ __align__(16) float g_cc[NB];
__device__ __align__(16) int   g_idx[NT];
__device__ __align__(16) float g_nsum[NB*Cdim];
__device__ __align__(16) float g_ncnt[NB];
__device__ float g_loss;
__device__ __align__(16) __half g_dhat[(size_t)NT * NB];  // 128 MB fp16 approx distances
__device__ __align__(16) float g_xT[(size_t)NT * Cdim];   // 64 MB x transposed [row][c]

// ---------------------------------------------------------------- helpers
__device__ __forceinline__ void cp_async16(uint32_t saddr, const void* g) {
    asm volatile("cp.async.ca.shared.global [%0], [%1], 16;" :: "r"(saddr), "l"(g));
}
__device__ __forceinline__ void cp_commit() {
    asm volatile("cp.async.commit_group;" ::: "memory");
}
__device__ __forceinline__ void mma_tf32(float* d, const uint32_t* a, const uint32_t* b) {
    asm volatile(
        "mma.sync.aligned.m16n8k8.row.col.f32.tf32.tf32.f32 "
        "{%0,%1,%2,%3}, {%4,%5,%6,%7}, {%8,%9}, {%0,%1,%2,%3};"
        : "+f"(d[0]), "+f"(d[1]), "+f"(d[2]), "+f"(d[3])
        : "r"(a[0]), "r"(a[1]), "r"(a[2]), "r"(a[3]), "r"(b[0]), "r"(b[1]));
}

// ---------------- 0: zero scratch ----------------
__global__ void zero_kernel() {
    int i = blockIdx.x * 256 + threadIdx.x;
    if (i < NB * Cdim) g_nsum[i] = 0.0f;
    if (i < NB)        g_ncnt[i] = 0.0f;
    if (i == 0)        g_loss = 0.0f;
}

// ---------------- 1: codebook squared norms ----------------
__global__ void norms_kernel(const float* __restrict__ cb) {
    int warp = threadIdx.x >> 5, lane = threadIdx.x & 31;
    int code = blockIdx.x * 8 + warp;
    const float* row = cb + (size_t)code * Cdim;
    float s = 0.0f;
    for (int j = lane; j < Cdim; j += 32) { float v = row[j]; s += v * v; }
    #pragma unroll
    for (int o = 16; o > 0; o >>= 1) s += __shfl_xor_sync(0xffffffffu, s, o);
    if (lane == 0) g_cc[code] = s;
}

// ---------------- 2: transpose x -> xT[row][c] ----------------
__global__ void transpose_kernel(const float* __restrict__ x) {
    __shared__ float s[32][33];
    int b = blockIdx.x;
    int ct = b & 15;          // c tile (16)
    int tt = (b >> 4) & 31;   // t tile (32)
    int n  = b >> 9;          // batch (32)
    int tid = threadIdx.x;
    int l5 = tid & 31, h3 = tid >> 5;
    #pragma unroll
    for (int q = 0; q < 4; q++) {
        int c_l = h3 + q * 8;
        s[c_l][l5] = x[(size_t)n * CT + (size_t)(ct * 32 + c_l) * Tdim + tt * 32 + l5];
    }
    __syncthreads();
    #pragma unroll
    for (int q = 0; q < 4; q++) {
        int t_l = h3 + q * 8;
        g_xT[(size_t)(n * 1024 + tt * 32 + t_l) * Cdim + ct * 32 + l5] = s[l5][t_l];
    }
}

// ---------------- 3: TF32 mma.sync screen GEMM -> d_hat (fp16) ----------------
// 3-stage cp.async pipeline, ONE barrier per iter. PROVEN 532us/42.5% binary — do not edit.
#define BM 128
#define BN 128
#define BK 32
#define AS_STRIDE 136
#define BS_STRIDE 36
#define AS_FLOATS (BK * AS_STRIDE)                 // 4352
#define BS_FLOATS (BN * BS_STRIDE)                 // 4608
#define STAGE_FLOATS (AS_FLOATS + BS_FLOATS)       // 8960
#define SMEM_BYTES (3 * STAGE_FLOATS * 4)          // 107520

__global__ __launch_bounds__(256, 2) void gemm_dhat(const float* __restrict__ x,
                                                    const float* __restrict__ cb) {
    extern __shared__ float sm[];
    uint32_t smbase = (uint32_t)__cvta_generic_to_shared(sm);

    int tid = threadIdx.x, lane = tid & 31, wid = tid >> 5;
    int wm = wid >> 2, wn = wid & 3;       // warp grid 2 (m) x 4 (n)
    int lq = lane & 3, lr = lane >> 2;
    int r0 = blockIdx.x * BM;
    const float* xb = x + (size_t)(r0 >> 10) * CT + (r0 & 1023);

    int a_p  = (tid & 31) << 2;  // float offset within a k-row (0..124)
    int a_kb = tid >> 5;         // base k (0..7)
    int b_kp = (tid & 7) << 2;   // float offset within code row
    int b_cb = tid >> 3;         // base code (0..31)

    float acc[4][4][4];
    #pragma unroll
    for (int mi = 0; mi < 4; mi++)
        #pragma unroll
        for (int ni = 0; ni < 4; ni++)
            #pragma unroll
            for (int v = 0; v < 4; v++) acc[mi][ni][v] = 0.0f;

    auto load_tiles = [&](int stage, int idx) {
        int nt = (idx >> 4) * 128, kc = (idx & 15) * 32;
        uint32_t sA = smbase + (uint32_t)(stage * STAGE_FLOATS) * 4u;
        uint32_t sB = sA + (uint32_t)AS_FLOATS * 4u;
        #pragma unroll
        for (int it = 0; it < 4; it++) {
            int k = a_kb + it * 8;
            cp_async16(sA + (uint32_t)(k * AS_STRIDE + a_p) * 4u,
                       xb + (size_t)(kc + k) * Tdim + a_p);
        }
        #pragma unroll
        for (int it = 0; it < 4; it++) {
            int code = b_cb + it * 32;
            cp_async16(sB + (uint32_t)(code * BS_STRIDE + b_kp) * 4u,
                       cb + (size_t)(nt + code) * Cdim + kc + b_kp);
        }
    };

    load_tiles(0, 0); cp_commit();
    load_tiles(1, 1); cp_commit();
    asm volatile("cp.async.wait_group 1;" ::: "memory");   // stage 0 landed (all threads, pre-bar)

    for (int i = 0; i < 256; i++) {            // (nt, kc) flattened: 16 x 16
        __syncthreads();                       // opens epoch i: stage i%3 published, overwrite-safe
        if (i + 2 < 256) load_tiles((i + 2) % 3, i + 2);
        cp_commit();
        asm volatile("cp.async.wait_group 1;" ::: "memory");  // data <= i+1 landed (this thread)

        const float* A = sm + (i % 3) * STAGE_FLOATS;
        const float* B = A + AS_FLOATS;
        #pragma unroll
        for (int kk = 0; kk < 4; kk++) {
            uint32_t a[4][4], b[4][2];
            #pragma unroll
            for (int mi = 0; mi < 4; mi++) {
                const float* ap = A + (kk * 8 + lq) * AS_STRIDE + wm * 64 + mi * 16 + lr;
                a[mi][0] = __float_as_uint(ap[0]);
                a[mi][1] = __float_as_uint(ap[8]);
                a[mi][2] = __float_as_uint(ap[4 * AS_STRIDE]);
                a[mi][3] = __float_as_uint(ap[4 * AS_STRIDE + 8]);
            }
            #pragma unroll
            for (int ni = 0; ni < 4; ni++) {
                const float* bp = B + (wn * 32 + ni * 8 + lr) * BS_STRIDE + kk * 8 + lq;
                b[ni][0] = __float_as_uint(bp[0]);
                b[ni][1] = __float_as_uint(bp[4]);
            }
            #pragma unroll
            for (int mi = 0; mi < 4; mi++)
                #pragma unroll
                for (int ni = 0; ni < 4; ni++)
                    mma_tf32(acc[mi][ni], a[mi], b[ni]);
        }

        if ((i & 15) == 15) {  // end of K for this n-tile: spill d_hat (fp16), reset accs
            int nt = (i >> 4) * 128;
            #pragma unroll
            for (int mi = 0; mi < 4; mi++) {
                int row = r0 + wm * 64 + mi * 16 + lr;
                #pragma unroll
                for (int ni = 0; ni < 4; ni++) {
                    int col = nt + wn * 32 + ni * 8 + 2 * lq;
                    float cc0 = __ldg(&g_cc[col]);
                    float cc1 = __ldg(&g_cc[col + 1]);
                    float2 v0 = make_float2(cc0 - 2.0f * acc[mi][ni][0],
                                            cc1 - 2.0f * acc[mi][ni][1]);
                    float2 v1 = make_float2(cc0 - 2.0f * acc[mi][ni][2],
                                            cc1 - 2.0f * acc[mi][ni][3]);
                    *(__half2*)&g_dhat[(size_t)row * NB + col] = __float22half2_rn(v0);
                    *(__half2*)&g_dhat[(size_t)(row + 8) * NB + col] = __float22half2_rn(v1);
                    acc[mi][ni][0] = acc[mi][ni][1] = acc[mi][ni][2] = acc[mi][ni][3] = 0.0f;
                }
            }
        }
    }
}

// ---------------- 4: rescue + fused segment-sum scatter ----------------
// Exact fp32 argmin among margin candidates; the true argmin is ALWAYS a
// candidate (d_hat(j*) <= d_hat_min + 2*delta < d_hat_min + 8), so a row with
// exactly ONE candidate needs no exact recompute. Then the row's xr registers
// feed the coalesced g_nsum atomics directly (rowscatter fused in).
__global__ void rescue_kernel(const float* __restrict__ cb) {
    int wid = threadIdx.x >> 5, lane = threadIdx.x & 31;
    int row = blockIdx.x * 8 + wid;

    float xr[16];
    #pragma unroll
    for (int q = 0; q < 16; q++)
        xr[q] = g_xT[(size_t)row * Cdim + lane + q * 32];

    const __half2* drow = (const __half2*)&g_dhat[(size_t)row * NB];
    float2 dv[32];
    #pragma unroll
    for (int i = 0; i < 32; i++)
        dv[i] = __half22float2(drow[lane + i * 32]);   // codes 2*(lane+i*32), +1

    float bv = fminf(dv[0].x, dv[0].y);
    #pragma unroll
    for (int i = 1; i < 32; i++) bv = fminf(bv, fminf(dv[i].x, dv[i].y));
    #pragma unroll
    for (int o = 16; o > 0; o >>= 1) bv = fminf(bv, __shfl_xor_sync(0xffffffffu, bv, o));

    float thr = bv + 8.0f;

    // pass 1: count candidates (uniform across warp); remember the first
    int count = 0;
    int firstj = -1;
    #pragma unroll
    for (int i = 0; i < 32; i++) {
        unsigned mlo = __ballot_sync(0xffffffffu, dv[i].x <= thr);
        unsigned mhi = __ballot_sync(0xffffffffu, dv[i].y <= thr);
        if (count == 0) {
            if (mlo)      firstj = (i * 32 + (__ffs(mlo) - 1)) * 2;
            else if (mhi) firstj = (i * 32 + (__ffs(mhi) - 1)) * 2 + 1;
        }
        count += __popc(mlo) + __popc(mhi);
    }

    int bestI;
    if (count == 1) {
        bestI = firstj;          // single candidate must be the true argmin
    } else {
        float bestE = 3.0e38f;
        bestI = 0x7fffffff;
        #pragma unroll 4
        for (int i = 0; i < 32; i++) {
            unsigned mlo = __ballot_sync(0xffffffffu, dv[i].x <= thr);
            unsigned mhi = __ballot_sync(0xffffffffu, dv[i].y <= thr);
            unsigned m2[2] = { mlo, mhi };
            #pragma unroll
            for (int h = 0; h < 2; h++) {
                unsigned m = m2[h];
                while (m) {
                    int s = __ffs(m) - 1;
                    m &= m - 1;
                    int j = (i * 32 + s) * 2 + h;
                    const float* crow = cb + (size_t)j * Cdim;
                    float p = 0.0f;
                    #pragma unroll
                    for (int q = 0; q < 16; q++)
                        p += xr[q] * __ldg(&crow[lane + q * 32]);
                    #pragma unroll
                    for (int o = 16; o > 0; o >>= 1) p += __shfl_xor_sync(0xffffffffu, p, o);
                    float d = __ldg(&g_cc[j]) - 2.0f * p;
                    if (d < bestE || (d == bestE && j < bestI)) { bestE = d; bestI = j; }
                }
            }
        }
    }

    // fused rowscatter: coalesced red.global into this code's nsum row
    float* dst = &g_nsum[(size_t)bestI * Cdim];
    #pragma unroll
    for (int q = 0; q < 16; q++)
        atomicAdd(&dst[lane + q * 32], xr[q]);
    if (lane == 0) {
        g_idx[row] = bestI;
        atomicAdd(&g_ncnt[bestI], 1.0f);
    }
}

// ---------------- 5: x_d output + commit-loss partial (no atomics on nsum) ----------------
__global__ void out_kernel(const float* __restrict__ x, const float* __restrict__ cb,
                           float* __restrict__ out) {
    int gi = (blockIdx.x * 256 + threadIdx.x) << 2;
    int n = gi >> 19;
    int rem = gi & (CT - 1);
    int c = rem >> 10;
    int t = rem & 1023;
    int row = (n << 10) + t;
    float4 xv = *(const float4*)(x + gi);
    int4 idx = *(const int4*)(g_idx + row);
    float4 o;
    o.x = cb[(size_t)idx.x * Cdim + c];
    o.y = cb[(size_t)idx.y * Cdim + c];
    o.z = cb[(size_t)idx.z * Cdim + c];
    o.w = cb[(size_t)idx.w * Cdim + c];
    *(float4*)(out + OFF_XD + gi) = o;
    float dx = xv.x - o.x, dy = xv.y - o.y, dz = xv.z - o.z, dw = xv.w - o.w;
    float s = dx * dx + dy * dy + dz * dz + dw * dw;
    #pragma unroll
    for (int off = 16; off > 0; off >>= 1) s += __shfl_xor_sync(0xffffffffu, s, off);
    __shared__ float sh[8];
    int lane = threadIdx.x & 31, w = threadIdx.x >> 5;
    if (lane == 0) sh[w] = s;
    __syncthreads();
    if (threadIdx.x == 0) {
        float tot = 0.0f;
        #pragma unroll
        for (int i = 0; i < 8; i++) tot += sh[i];
        atomicAdd(&g_loss, tot);
    }
}

// ---------------- 6: EMA update + codebook reset + count out ----------------
__global__ void ema_kernel(const float* __restrict__ x,
                           const float* __restrict__ code_sum,
                           const float* __restrict__ code_count,
                           float* __restrict__ out) {
    int gi = blockIdx.x * 256 + threadIdx.x;
    int code = gi >> 9;
    int c = gi & 511;
    float cse = 0.99f * code_sum[gi] + 0.01f * g_nsum[gi];
    float cnt = 0.99f * code_count[code] + 0.01f * g_ncnt[code];
    out[OFF_CSE + gi] = cse;
    float ncb;
    if (cnt >= 1.0f) {
        ncb = cse / fmaxf(cnt, 1e-10f);
    } else {
        int t = code & 1023;
        int n = code >> 10;
        ncb = x[(size_t)n * CT + (size_t)c * Tdim + t];
    }
    out[OFF_CB + gi] = ncb;
    if (c == 0) out[OFF_CNT + code] = cnt;
}

// ---------------- 7: perplexity + loss finalize ----------------
__global__ void finalize_kernel(float* __restrict__ out) {
    float h = 0.0f;
    for (int code = threadIdx.x; code < NB; code += 256) {
        float p = g_ncnt[code] * (1.0f / 32768.0f);
        h += p * logf(p + 1e-7f);
    }
    #pragma unroll
    for (int off = 16; off > 0; off >>= 1) h += __shfl_xor_sync(0xffffffffu, h, off);
    __shared__ float sh[8];
    int lane = threadIdx.x & 31, w = threadIdx.x >> 5;
    if (lane == 0) sh[w] = h;
    __syncthreads();
    if (threadIdx.x == 0) {
        float tot = 0.0f;
        #pragma unroll
        for (int i = 0; i < 8; i++) tot += sh[i];
        out[OFF_PERP] = expf(-tot);
        out[OFF_LOSS] = g_loss * (1.0f / (float)XSZ);
    }
}

extern "C" void kernel_launch(void* const* d_in, const int* in_sizes, int n_in,
                              void* d_out, int out_size) {
    const float* x    = (const float*)d_in[0];
    const float* cb   = (const float*)d_in[1];
    const float* csum = (const float*)d_in[2];
    const float* ccnt = (const float*)d_in[3];
    float* out = (float*)d_out;

    cudaFuncSetAttribute(gemm_dhat, cudaFuncAttributeMaxDynamicSharedMemorySize, SMEM_BYTES);

    zero_kernel      <<<(NB * Cdim + 255) / 256, 256>>>();
    norms_kernel     <<<NB / 8, 256>>>(cb);
    transpose_kernel <<<Ndim * 32 * 16, 256>>>(x);
    gemm_dhat        <<<NT / BM, 256, SMEM_BYTES>>>(x, cb);
    rescue_kernel    <<<NT / 8, 256>>>(cb);
    out_kernel       <<<XSZ / 4 / 256, 256>>>(x, cb, out);
    ema_kernel       <<<NB * Cdim / 256, 256>>>(x, csum, ccnt, out);
    finalize_kernel  <<<1, 256>>>(out);
}